// round 16
// baseline (speedup 1.0000x reference)
#include <cuda_runtime.h>

#define H 64
#define KCH 24
#define THREADS 256
#define CHG 8                      // channels per CTA (two quad passes)
#define NW  600                    // weights per channel (24*25)

// ---------------------------------------------------------------------------
// One CTA per (channel-octet, batch). Row-list gather; each quad of channels
// shares every entry decode via interleaved float4 weights (1 LDS.128 feeds
// 4 channel accumulators). Two quad passes reuse the row lists; the second
// quad's weights are prefetched during the first quad's gather.
// ---------------------------------------------------------------------------
__global__ __launch_bounds__(THREADS, 5)
void gauss_oct_kernel(const float* __restrict__ x,
                      const float* __restrict__ weight,
                      const int*  __restrict__ vis_batch,
                      const int*  __restrict__ vis_kps,
                      int n_vis,
                      float* __restrict__ out)
{
    const int o0  = blockIdx.x * CHG;   // first channel of octet
    const int b   = blockIdx.y;         // batch
    const int tid = threadIdx.x;

    __shared__ float4 wq4[2][NW];       // interleaved weights per quad (2x9.6KB)
    __shared__ int    cnt[H];           // taps hitting each output row
    __shared__ int    ent[H * KCH];     // per-row entries: (wb<<8)|xk (wb=k*25+dy*5)
    __shared__ int    killS[KCH];

    if (tid < H)   cnt[tid]  = 0;
    if (tid < KCH) killS[tid] = 0;
    __syncthreads();

    // vis-kill scan (1KB tables, L2-hot)
    for (int i = tid; i < n_vis; i += THREADS)
        if (__ldg(&vis_batch[i]) == b) killS[__ldg(&vis_kps[i])] = 1;

    // quad-0 interleaved weight load: wq4[0][widx] = {w[o0..o0+3][widx]}
    // (lane pattern touches 4x32B sectors per warp LDG — fully sector-efficient)
    {
        const float* wsrc = weight + (size_t)o0 * NW;
        float* wqf = (float*)wq4[0];
        for (int i = tid; i < NW * 4; i += THREADS)
            wqf[i] = __ldg(&wsrc[(size_t)(i & 3) * NW + (i >> 2)]);
    }

    // coords + torch quirk + invalid masking; build per-row lists.
    // lax conv = cross-correlation: out[yk+2-dy, xk+2-dx] += w[o,k,dy,dx]
    if (tid < KCH) {
        float fx = __ldg(&x[((size_t)b * KCH + tid) * 2 + 0]);
        float fy = __ldg(&x[((size_t)b * KCH + tid) * 2 + 1]);
        // match JAX: round(((x+1)*0.5)*(H-1)), banker's rounding
        int cx = (int)rintf(((fx + 1.0f) * 0.5f) * (float)(H - 1));
        int cy = (int)rintf(((fy + 1.0f) * 0.5f) * (float)(H - 1));
        // invalid -> coords zeroed -> cx==0 -> inactive; quirk: cx != 0
        bool act = ((unsigned)cx < (unsigned)H) && ((unsigned)cy < (unsigned)H)
                   && (cx != 0) && (!killS[tid]);
        if (act) {
            int wb = tid * 25;
            #pragma unroll
            for (int dy = 0; dy < 5; dy++) {
                int r = cy + 2 - dy;
                if ((unsigned)r < (unsigned)H) {
                    int s = atomicAdd(&cnt[r], 1);
                    ent[r * KCH + s] = ((wb + dy * 5) << 8) | cx;
                }
            }
        }
    }
    __syncthreads();

    // Thread -> pixels: 4 groups of 4 consecutive px (rows R0+16i, cols c0..c0+3);
    // every STG.128 below is a fully coalesced 512B warp transaction.
    const int R0 = tid >> 4;
    const int c0 = (tid & 15) << 2;

    #pragma unroll
    for (int q = 0; q < 2; q++) {
        // prefetch the other quad's weights during quad-0's gather
        if (q == 0) {
            const float* wsrc = weight + (size_t)(o0 + 4) * NW;
            float* wqf = (float*)wq4[1];
            for (int i = tid; i < NW * 4; i += THREADS)
                wqf[i] = __ldg(&wsrc[(size_t)(i & 3) * NW + (i >> 2)]);
        }

        const float4* __restrict__ wq = wq4[q];
        float* const obase = out + (((size_t)b * KCH + o0 + 4 * q) << 12);

        #pragma unroll
        for (int i = 0; i < 4; i++) {
            const int r = R0 + (i << 4);
            const int n = cnt[r];
            const int* el = &ent[r * KCH];
            float4 a0 = make_float4(0.f,0.f,0.f,0.f);
            float4 a1 = make_float4(0.f,0.f,0.f,0.f);
            float4 a2 = make_float4(0.f,0.f,0.f,0.f);
            float4 a3 = make_float4(0.f,0.f,0.f,0.f);
            for (int e = 0; e < n; e++) {
                int v  = el[e];
                int d0 = (v & 255) + 2 - c0;   // dx for col c0; col c0+j uses d0-j
                int wb = v >> 8;
                if ((unsigned)(d0    ) <= 4u) { float4 wv = wq[wb + d0    ];
                    a0.x += wv.x; a1.x += wv.y; a2.x += wv.z; a3.x += wv.w; }
                if ((unsigned)(d0 - 1) <= 4u) { float4 wv = wq[wb + d0 - 1];
                    a0.y += wv.x; a1.y += wv.y; a2.y += wv.z; a3.y += wv.w; }
                if ((unsigned)(d0 - 2) <= 4u) { float4 wv = wq[wb + d0 - 2];
                    a0.z += wv.x; a1.z += wv.y; a2.z += wv.z; a3.z += wv.w; }
                if ((unsigned)(d0 - 3) <= 4u) { float4 wv = wq[wb + d0 - 3];
                    a0.w += wv.x; a1.w += wv.y; a2.w += wv.z; a3.w += wv.w; }
            }
            const int fi = (i << 8) + tid;
            __stcs((float4*)(obase            ) + fi, a0);
            __stcs((float4*)(obase + (1 << 12)) + fi, a1);
            __stcs((float4*)(obase + (2 << 12)) + fi, a2);
            __stcs((float4*)(obase + (3 << 12)) + fi, a3);
        }

        if (q == 0) __syncthreads();   // wq4[1] prefetch visible before pass 1
    }
}

extern "C" void kernel_launch(void* const* d_in, const int* in_sizes, int n_in,
                              void* d_out, int out_size)
{
    const float* x      = (const float*)d_in[0];
    const float* weight = (const float*)d_in[1];
    const int*   vb     = (const int*)d_in[2];
    const int*   vk     = (const int*)d_in[3];
    float*       out    = (float*)d_out;

    int n_vis = in_sizes[2];
    int B     = in_sizes[0] / (KCH * 2);   // 1024

    dim3 grid(KCH / CHG, B);               // (3, 1024)
    gauss_oct_kernel<<<grid, THREADS>>>(x, weight, vb, vk, n_vis, out);
}